// round 2
// baseline (speedup 1.0000x reference)
#include <cuda_runtime.h>
#include <math.h>

// Problem constants
#define U_N 512
#define P_N 1024
#define N_N 1536
#define D_D 128
#define H_H 256
#define E_E 98304

// ---------------- scratch (static __device__, no allocs) ----------------
__device__ int   g_deg[N_N];
__device__ float g_dis[N_N];
__device__ int   g_off[N_N + 1];
__device__ int   g_cur[N_N];
__device__ int   g_csrc[E_E];
__device__ float g_cnorm[E_E];
__device__ float g_x0[N_N * D_D];
__device__ float g_h [N_N * H_H];
__device__ float g_x [N_N * H_H];
__device__ float g_uf[U_N * D_D];
__device__ float g_pf[P_N * D_D];
__device__ float g_A [U_N * H_H];
__device__ float g_B [P_N * H_H];

// ---------------- graph build ----------------
__global__ void zero_kernel() {
    int i = blockIdx.x * blockDim.x + threadIdx.x;
    if (i < N_N) { g_deg[i] = 0; g_cur[i] = 0; }
}

__global__ void count_kernel(const int* __restrict__ ei) {
    int e = blockIdx.x * blockDim.x + threadIdx.x;
    if (e < E_E) {
        int d = ei[E_E + e];
        atomicAdd(&g_deg[d], 1);
    }
}

// single block: dis + exclusive prefix sum of edge-degrees
__global__ void scan_kernel() {
    __shared__ int vals[N_N];
    __shared__ int psum[512];
    int t = threadIdx.x;
    for (int i = t; i < N_N; i += 512) {
        int v = g_deg[i];
        vals[i] = v;
        g_dis[i] = rsqrtf((float)(v + 1));   // +1 self loop
    }
    __syncthreads();
    int base = t * 3;
    int s0 = vals[base], s1 = vals[base + 1], s2 = vals[base + 2];
    int loc = s0 + s1 + s2;
    psum[t] = loc;
    __syncthreads();
    for (int off = 1; off < 512; off <<= 1) {
        int v = 0;
        if (t >= off) v = psum[t - off];
        __syncthreads();
        psum[t] += v;
        __syncthreads();
    }
    int excl = psum[t] - loc;
    g_off[base]     = excl;
    g_off[base + 1] = excl + s0;
    g_off[base + 2] = excl + s0 + s1;
    if (t == 511) g_off[N_N] = psum[511];
}

__global__ void scatter_kernel(const int* __restrict__ ei) {
    int e = blockIdx.x * blockDim.x + threadIdx.x;
    if (e < E_E) {
        int s = ei[e];
        int d = ei[E_E + e];
        int slot = g_off[d] + atomicAdd(&g_cur[d], 1);
        g_csrc[slot]  = s;
        g_cnorm[slot] = g_dis[s] * g_dis[d];
    }
}

// ---------------- node features ----------------
__global__ void gather_x0_kernel(const int* __restrict__ uid,
                                 const int* __restrict__ pid,
                                 const float* __restrict__ uemb,
                                 const float* __restrict__ pemb) {
    int idx = blockIdx.x * blockDim.x + threadIdx.x;   // N*32 float4s
    if (idx >= N_N * (D_D / 4)) return;
    int i = idx >> 5;        // node
    int dd = (idx & 31) * 4;
    float4 v;
    if (i < U_N) v = *(const float4*)&uemb[uid[i] * D_D + dd];
    else         v = *(const float4*)&pemb[pid[i - U_N] * D_D + dd];
    *(float4*)&g_x0[i * D_D + dd] = v;
}

// ---------------- generic SGEMM: C[M,N] = X[M,K] @ W[K,N] (+bias) ----------------
// 64x64 tile, 256 threads, 4x4 micro-tile, K-chunk 16. M,N multiples of 64, K of 16.
__global__ __launch_bounds__(256) void sgemm_kernel(
    const float* __restrict__ X, const float* __restrict__ W,
    const float* __restrict__ bias, float* __restrict__ C,
    int M, int K, int N)
{
    __shared__ float Xs[16][68];   // [k][m], padded (68*4=272, 16B-aligned rows)
    __shared__ float Ws[16][68];   // [k][n]

    int t  = threadIdx.x;
    int tx = t & 15;       // n micro
    int ty = t >> 4;       // m micro
    int m0 = blockIdx.y * 64;
    int n0 = blockIdx.x * 64;

    float acc[4][4];
#pragma unroll
    for (int i = 0; i < 4; i++)
#pragma unroll
        for (int j = 0; j < 4; j++) acc[i][j] = 0.0f;

    int xk = t & 15;       // k for X load
    int xm = t >> 4;       // m base for X load
    int wn = t & 63;       // n for W load
    int wk = t >> 6;       // k base for W load

    for (int kt = 0; kt < K; kt += 16) {
#pragma unroll
        for (int it = 0; it < 4; it++) {
            int mm = xm + 16 * it;
            Xs[xk][mm] = X[(m0 + mm) * K + kt + xk];
        }
#pragma unroll
        for (int it = 0; it < 4; it++) {
            int kk = wk + 4 * it;
            Ws[kk][wn] = W[(kt + kk) * N + n0 + wn];
        }
        __syncthreads();
#pragma unroll
        for (int kk = 0; kk < 16; kk++) {
            float4 a = *(const float4*)&Xs[kk][ty * 4];
            float4 b = *(const float4*)&Ws[kk][tx * 4];
            acc[0][0] = fmaf(a.x, b.x, acc[0][0]);
            acc[0][1] = fmaf(a.x, b.y, acc[0][1]);
            acc[0][2] = fmaf(a.x, b.z, acc[0][2]);
            acc[0][3] = fmaf(a.x, b.w, acc[0][3]);
            acc[1][0] = fmaf(a.y, b.x, acc[1][0]);
            acc[1][1] = fmaf(a.y, b.y, acc[1][1]);
            acc[1][2] = fmaf(a.y, b.z, acc[1][2]);
            acc[1][3] = fmaf(a.y, b.w, acc[1][3]);
            acc[2][0] = fmaf(a.z, b.x, acc[2][0]);
            acc[2][1] = fmaf(a.z, b.y, acc[2][1]);
            acc[2][2] = fmaf(a.z, b.z, acc[2][2]);
            acc[2][3] = fmaf(a.z, b.w, acc[2][3]);
            acc[3][0] = fmaf(a.w, b.x, acc[3][0]);
            acc[3][1] = fmaf(a.w, b.y, acc[3][1]);
            acc[3][2] = fmaf(a.w, b.z, acc[3][2]);
            acc[3][3] = fmaf(a.w, b.w, acc[3][3]);
        }
        __syncthreads();
    }

    // vectorized epilogue: 4 consecutive columns per thread -> float4 stores
    float4 bv = make_float4(0.f, 0.f, 0.f, 0.f);
    if (bias) bv = *(const float4*)&bias[n0 + tx * 4];
#pragma unroll
    for (int i = 0; i < 4; i++) {
        int m = m0 + ty * 4 + i;
        float4 o;
        o.x = acc[i][0] + bv.x;
        o.y = acc[i][1] + bv.y;
        o.z = acc[i][2] + bv.z;
        o.w = acc[i][3] + bv.w;
        *(float4*)&C[m * N + n0 + tx * 4] = o;
    }
}

// ---------------- GCN aggregation (gather form, float4 lanes) ----------------
// out[n,f] = relu( h[n,f]*dis[n]^2 + sum_e h[src_e,f]*norm_e + b[f] )
// 64 threads per node; each thread owns 4 consecutive features.
__global__ __launch_bounds__(64) void aggregate_kernel(
    const float* __restrict__ h, const float* __restrict__ bias,
    float* __restrict__ xout)
{
    __shared__ int   ssrc[64];
    __shared__ float snorm[64];
    int n = blockIdx.x;
    int t = threadIdx.x;           // 0..63
    int f = t * 4;
    float dn = g_dis[n];
    float s2 = dn * dn;
    float4 hv = *(const float4*)&h[n * H_H + f];
    float4 acc;
    acc.x = hv.x * s2; acc.y = hv.y * s2; acc.z = hv.z * s2; acc.w = hv.w * s2;

    int beg = g_off[n], end = g_off[n + 1];
    for (int c = beg; c < end; c += 64) {
        int cnt = min(64, end - c);
        if (t < cnt) { ssrc[t] = g_csrc[c + t]; snorm[t] = g_cnorm[c + t]; }
        __syncthreads();
#pragma unroll 4
        for (int k = 0; k < cnt; k++) {
            float  w = snorm[k];
            float4 v = *(const float4*)&h[ssrc[k] * H_H + f];
            acc.x = fmaf(v.x, w, acc.x);
            acc.y = fmaf(v.y, w, acc.y);
            acc.z = fmaf(v.z, w, acc.z);
            acc.w = fmaf(v.w, w, acc.w);
        }
        __syncthreads();
    }
    float4 b = *(const float4*)&bias[f];
    float4 o;
    o.x = fmaxf(acc.x + b.x, 0.0f);
    o.y = fmaxf(acc.y + b.y, 0.0f);
    o.z = fmaxf(acc.z + b.z, 0.0f);
    o.w = fmaxf(acc.w + b.w, 0.0f);
    *(float4*)&xout[n * H_H + f] = o;
}

// ---------------- fused predictor ----------------
// pred[u,p] = sigmoid( sum_h relu(A[u,h]+B[p,h]) * Wq2[h] + bq2 )
// (bq1 folded into A)
__global__ __launch_bounds__(256) void predict_kernel(
    const float* __restrict__ Wq2, const float* __restrict__ bq2,
    float* __restrict__ out)
{
    __shared__ float sA[64][68];   // [h][u]
    __shared__ float sB[64][68];   // [h][p]
    __shared__ float sW[64];

    int t  = threadIdx.x;
    int tx = t & 15;   // paper micro
    int ty = t >> 4;   // user micro
    int u0 = blockIdx.y * 64;
    int p0 = blockIdx.x * 64;

    float acc[4][4];
#pragma unroll
    for (int i = 0; i < 4; i++)
#pragma unroll
        for (int j = 0; j < 4; j++) acc[i][j] = 0.0f;

    int lh = t & 63;   // h for loads (coalesced)
    int lr = t >> 6;   // row base

    for (int h0 = 0; h0 < H_H; h0 += 64) {
#pragma unroll
        for (int it = 0; it < 16; it++) {
            int r = lr + 4 * it;
            sA[lh][r] = g_A[(u0 + r) * H_H + h0 + lh];
            sB[lh][r] = g_B[(p0 + r) * H_H + h0 + lh];
        }
        if (t < 64) sW[t] = Wq2[h0 + t];
        __syncthreads();
#pragma unroll
        for (int hh = 0; hh < 64; hh++) {
            float w = sW[hh];
            float4 a = *(const float4*)&sA[hh][ty * 4];
            float4 b = *(const float4*)&sB[hh][tx * 4];
            float av[4] = {a.x, a.y, a.z, a.w};
            float bv[4] = {b.x, b.y, b.z, b.w};
#pragma unroll
            for (int i = 0; i < 4; i++)
#pragma unroll
                for (int j = 0; j < 4; j++) {
                    float v = fmaxf(av[i] + bv[j], 0.0f);
                    acc[i][j] = fmaf(v, w, acc[i][j]);
                }
        }
        __syncthreads();
    }

    float c = bq2[0];
#pragma unroll
    for (int i = 0; i < 4; i++) {
        int u = u0 + ty * 4 + i;
        float4 o;
        float z0 = acc[i][0] + c, z1 = acc[i][1] + c;
        float z2 = acc[i][2] + c, z3 = acc[i][3] + c;
        o.x = 1.0f / (1.0f + __expf(-z0));
        o.y = 1.0f / (1.0f + __expf(-z1));
        o.z = 1.0f / (1.0f + __expf(-z2));
        o.w = 1.0f / (1.0f + __expf(-z3));
        *(float4*)&out[u * P_N + p0 + tx * 4] = o;
    }
}

// ---------------- launch ----------------
extern "C" void kernel_launch(void* const* d_in, const int* in_sizes, int n_in,
                              void* d_out, int out_size)
{
    const int*   uid  = (const int*)  d_in[0];
    const int*   pid  = (const int*)  d_in[1];
    const int*   ei   = (const int*)  d_in[2];
    // d_in[3] = user_paper_interactions (unused by reference)
    const float* uemb = (const float*)d_in[4];
    const float* pemb = (const float*)d_in[5];
    const float* W0   = (const float*)d_in[6];
    const float* b0   = (const float*)d_in[7];
    const float* W1   = (const float*)d_in[8];
    const float* b1   = (const float*)d_in[9];
    const float* W2   = (const float*)d_in[10];
    const float* b2   = (const float*)d_in[11];
    const float* Wu   = (const float*)d_in[12];
    const float* bu   = (const float*)d_in[13];
    const float* Wp   = (const float*)d_in[14];
    const float* bp   = (const float*)d_in[15];
    const float* Wq1  = (const float*)d_in[16];
    const float* bq1  = (const float*)d_in[17];
    const float* Wq2  = (const float*)d_in[18];
    const float* bq2  = (const float*)d_in[19];
    float* out = (float*)d_out;

    // device-global pointers (host API query; not a stream op, capture-safe)
    float *x0, *h, *x, *uf, *pf, *A, *B;
    cudaGetSymbolAddress((void**)&x0, g_x0);
    cudaGetSymbolAddress((void**)&h,  g_h);
    cudaGetSymbolAddress((void**)&x,  g_x);
    cudaGetSymbolAddress((void**)&uf, g_uf);
    cudaGetSymbolAddress((void**)&pf, g_pf);
    cudaGetSymbolAddress((void**)&A,  g_A);
    cudaGetSymbolAddress((void**)&B,  g_B);

    // ---- graph build ----
    zero_kernel<<<(N_N + 255) / 256, 256>>>();
    count_kernel<<<(E_E + 255) / 256, 256>>>(ei);
    scan_kernel<<<1, 512>>>();
    scatter_kernel<<<(E_E + 255) / 256, 256>>>(ei);

    // ---- node features ----
    gather_x0_kernel<<<(N_N * (D_D / 4) + 255) / 256, 256>>>(uid, pid, uemb, pemb);

    // ---- 3 GCN layers ----
    dim3 blk(256);
    sgemm_kernel<<<dim3(H_H / 64, N_N / 64), blk>>>(x0, W0, nullptr, h, N_N, D_D, H_H);
    aggregate_kernel<<<N_N, 64>>>(h, b0, x);
    sgemm_kernel<<<dim3(H_H / 64, N_N / 64), blk>>>(x, W1, nullptr, h, N_N, H_H, H_H);
    aggregate_kernel<<<N_N, 64>>>(h, b1, x);
    sgemm_kernel<<<dim3(H_H / 64, N_N / 64), blk>>>(x, W2, nullptr, h, N_N, H_H, H_H);
    aggregate_kernel<<<N_N, 64>>>(h, b2, x);

    // ---- output heads ----
    sgemm_kernel<<<dim3(D_D / 64, U_N / 64), blk>>>(x,             Wu, bu, uf, U_N, H_H, D_D);
    sgemm_kernel<<<dim3(D_D / 64, P_N / 64), blk>>>(x + U_N * H_H, Wp, bp, pf, P_N, H_H, D_D);

    // ---- factored predictor: A = uf@Wq1_top + bq1 ; B = pf@Wq1_bot ----
    sgemm_kernel<<<dim3(H_H / 64, U_N / 64), blk>>>(uf, Wq1,              bq1,     A, U_N, D_D, H_H);
    sgemm_kernel<<<dim3(H_H / 64, P_N / 64), blk>>>(pf, Wq1 + D_D * H_H,  nullptr, B, P_N, D_D, H_H);

    predict_kernel<<<dim3(P_N / 64, U_N / 64), blk>>>(Wq2, bq2, out);
}